// round 9
// baseline (speedup 1.0000x reference)
#include <cuda_runtime.h>
#include <cuda_fp16.h>
#include <stdint.h>
#include <math.h>

#define NS 48
#define NV 10
#define NE 100000
#define NN 10000
#define NF 144
#define IND 78
#define WNUM 3364
#define EPB 128
#define NBLK ((NE + EPB - 1) / EPB)
#define NCH 71
#define A_SS 0.102062072615966f
#define A_VV 0.223606797749979f
#define ISQ3 0.577350269189626f
#define EPSF 1e-5f

/* ---- SMEM byte offsets (k_main) ---- */
#define OFF_CS  0           /* [128][58] f32 = 29696 */
#define OFF_U   29696       /* [128][48] f32 = 24576 */
#define OFF_V   54272       /* [128][30] f32 = 15360 */
#define OFF_S0  69632       /* [128] f32 */
#define OFF_S1  70144       /* [128][3] f32 */
#define OFF_SS  71680       /* [128] int */
#define OFF_AP  72192       /* [128][10] f32 */
#define OFF_AQ  77312       /* [128][30] f32 */
#define SMEMTOT 92672

#define NLIN (NCH * 9)              /* 639 kt-steps */
#define WFRAG_N ((NLIN + 4) * 192)  /* uint4 count, padded for prefetch overrun */

__device__ float g_h[(size_t)NE * NF];
__device__ uint4 g_wfrag[WFRAG_N];  /* [lin][cg][r][lane] = {hb0,hb1,lb0,lb1} */
__device__ float g_sum[NN * IND];
__device__ float g_cnt[NN];
__device__ float g_pre[NN * IND];
__device__ float g_stat[2 * NS + NV];
__device__ float g_nrm[2 * NS + NV];

__device__ __forceinline__ void mma16816(float* d, const uint32_t* a,
                                         uint32_t b0, uint32_t b1) {
    asm volatile("mma.sync.aligned.m16n8k16.row.col.f32.f16.f16.f32 "
                 "{%0,%1,%2,%3}, {%4,%5,%6,%7}, {%8,%9}, {%0,%1,%2,%3};"
                 : "+f"(d[0]), "+f"(d[1]), "+f"(d[2]), "+f"(d[3])
                 : "r"(a[0]), "r"(a[1]), "r"(a[2]), "r"(a[3]), "r"(b0), "r"(b1));
}
__device__ __forceinline__ uint32_t pkh(float x0, float x1) {
    __half h0 = __float2half_rn(x0), h1 = __float2half_rn(x1);
    return (uint32_t)__half_as_ushort(h0) | ((uint32_t)__half_as_ushort(h1) << 16);
}

/* -------- w2 -> fp16 hi/lo fragment-order blob -------- */
__global__ void k_wprep(const float* __restrict__ w2) {
    int x = blockIdx.x * blockDim.x + threadIdx.x;
    if (x >= NLIN * 192) return;
    int lane = x & 31, t = x >> 5;
    int r = t % 3; t /= 3;
    int cgv = t & 1; int lin = t >> 1;
    int cc = lin / 9, kt = lin - cc * 9;
    int gc = cc * 48 + cgv * 24 + r * 8 + (lane >> 2);
    int k0 = kt * 16 + (lane & 3) * 2;
    float f[4];
#pragma unroll
    for (int q = 0; q < 4; q++) {
        int k = k0 + (q >> 1) * 8 + (q & 1);
        f[q] = (gc < WNUM) ? w2[(size_t)k * WNUM + gc] : 0.f;
    }
    __half h[4]; float l[4];
#pragma unroll
    for (int q = 0; q < 4; q++) { h[q] = __float2half_rn(f[q]); l[q] = f[q] - __half2float(h[q]); }
    uint4 o;
    o.x = (uint32_t)__half_as_ushort(h[0]) | ((uint32_t)__half_as_ushort(h[1]) << 16);
    o.y = (uint32_t)__half_as_ushort(h[2]) | ((uint32_t)__half_as_ushort(h[3]) << 16);
    o.z = pkh(l[0], l[1]);
    o.w = pkh(l[2], l[3]);
    g_wfrag[x] = o;
}

/* ---------------- fc1 + relu -> g_h (FFMA fp32) ---------------- */
__global__ __launch_bounds__(256, 1) void k_fc1(const float* __restrict__ ea,
                                                const float* __restrict__ w1,
                                                const float* __restrict__ b1) {
    extern __shared__ float sm[];
    float* sE = sm;            /* [144][132] */
    float* sW = sm + 19008;    /* [144][144] */
    int tid = threadIdx.x, tx = tid & 7, ty = tid >> 3;
    int e0 = blockIdx.x * EPB;

    for (int x = tid; x < EPB * NF; x += 256) {
        int e = x / NF, k = x - e * NF;
        sE[k * 132 + e] = (e0 + e < NE) ? ea[(size_t)(e0 + e) * NF + k] : 0.f;
    }
    for (int x = tid; x < NF * NF; x += 256) sW[x] = w1[x];
    __syncthreads();

    float acc[4][18];
#pragma unroll
    for (int r = 0; r < 4; r++)
#pragma unroll
        for (int j = 0; j < 18; j++) acc[r][j] = 0.f;

    for (int k = 0; k < NF; k++) {
        float4 hv = *(const float4*)&sE[k * 132 + ty * 4];
        float wv[18];
#pragma unroll
        for (int j = 0; j < 18; j++) wv[j] = sW[k * NF + tx * 18 + j];
#pragma unroll
        for (int j = 0; j < 18; j++) {
            acc[0][j] = fmaf(hv.x, wv[j], acc[0][j]);
            acc[1][j] = fmaf(hv.y, wv[j], acc[1][j]);
            acc[2][j] = fmaf(hv.z, wv[j], acc[2][j]);
            acc[3][j] = fmaf(hv.w, wv[j], acc[3][j]);
        }
    }
#pragma unroll
    for (int r = 0; r < 4; r++) {
        int e = e0 + ty * 4 + r;
        if (e < NE) {
#pragma unroll
            for (int j = 0; j < 18; j++) {
                int o = tx * 18 + j;
                g_h[(size_t)e * NF + o] = fmaxf(acc[r][j] + b1[o], 0.f);
            }
        }
    }
}

/* -------- fused fc2: fp16 mma 2-product, A-in-regs, fragment-stream B -------- */
__global__ __launch_bounds__(256, 1) void k_main(const float* __restrict__ na,
                                                 const float* __restrict__ esh,
                                                 const float* __restrict__ b2,
                                                 const int* __restrict__ ei) {
    extern __shared__ char smc[];
    float* sCS = (float*)(smc + OFF_CS);
    float* sU  = (float*)(smc + OFF_U);
    float* sV  = (float*)(smc + OFF_V);
    float* s0  = (float*)(smc + OFF_S0);
    float* s1  = (float*)(smc + OFF_S1);
    int*   sS  = (int*)(smc + OFF_SS);
    float* aP  = (float*)(smc + OFF_AP);
    float* aQ  = (float*)(smc + OFF_AQ);

    int tid = threadIdx.x, lane = tid & 31, warp = tid >> 5;
    int gid = lane >> 2, tig = lane & 3;
    int eg = warp >> 1, cg = warp & 1;
    int e0 = blockIdx.x * EPB;

    /* smem prep */
    for (int x = tid; x < EPB * IND; x += 256) {
        int e = x / IND, d = x - e * IND;
        float v = 0.f;
        if (e0 + e < NE) { int dst = ei[NE + e0 + e]; v = na[dst * IND + d]; }
        if (d < NS) sU[e * NS + d] = A_SS * v;
        else        sV[e * 30 + d - NS] = A_VV * v;
    }
    if (tid < EPB) {
        int egl = e0 + tid;
        if (egl < NE) {
            sS[tid] = ei[egl]; s0[tid] = esh[egl * 4];
            s1[tid * 3] = esh[egl * 4 + 1]; s1[tid * 3 + 1] = esh[egl * 4 + 2];
            s1[tid * 3 + 2] = esh[egl * 4 + 3];
        } else {
            sS[tid] = 0; s0[tid] = 0.f;
            s1[tid * 3] = s1[tid * 3 + 1] = s1[tid * 3 + 2] = 0.f;
        }
    }
    for (int x = tid; x < EPB * 40; x += 256) aP[x] = 0.f;  /* aP,aQ contiguous */
    __syncthreads();
    for (int x = tid; x < EPB * 58; x += 256) {
        int e = x / 58, i = x - e * 58;
        if (i < 48) sCS[x] = s0[e] * sU[e * 48 + i];
        else {
            int ii = i - 48;
            sCS[x] = ISQ3 * (sV[e * 30 + ii * 3] * s1[e * 3] +
                             sV[e * 30 + ii * 3 + 1] * s1[e * 3 + 1] +
                             sV[e * 30 + ii * 3 + 2] * s1[e * 3 + 2]);
        }
    }
    __syncthreads();

    /* A fragments in registers, chunk-invariant, fp16 */
    uint32_t AH[2][9][4];
#pragma unroll
    for (int mt = 0; mt < 2; mt++) {
        int r0 = eg * 32 + mt * 16 + gid;
#pragma unroll
        for (int kt = 0; kt < 9; kt++) {
#pragma unroll
            for (int q = 0; q < 4; q++) {
                int row = r0 + (q & 1) * 8;
                int k = kt * 16 + tig * 2 + (q >> 1) * 8;
                float f0 = 0.f, f1 = 0.f;
                if (e0 + row < NE) {
                    const float* p = &g_h[(size_t)(e0 + row) * NF + k];
                    f0 = p[0]; f1 = p[1];
                }
                AH[mt][kt][q] = pkh(f0, f1);
            }
        }
    }

    float acc[2][3][4];
#pragma unroll
    for (int mt = 0; mt < 2; mt++)
#pragma unroll
        for (int nt = 0; nt < 3; nt++)
#pragma unroll
            for (int q = 0; q < 4; q++) acc[mt][nt][q] = 0.f;

    /* fragment stream: idx(lin,r) = ((lin*2+cg)*3+r)*32+lane */
#define WIDX(l, r) (((((l) * 2 + cg) * 3 + (r)) << 5) + lane)
    uint4 buf[3][3];
#pragma unroll
    for (int l = 0; l < 3; l++) {
        buf[l][0] = g_wfrag[WIDX(l, 0)];
        buf[l][1] = g_wfrag[WIDX(l, 1)];
        buf[l][2] = g_wfrag[WIDX(l, 2)];
    }

    for (int cc = 0; cc < NCH; cc++) {
        int base = cc * 9;
        float d[2][3][4];
#pragma unroll
        for (int mt = 0; mt < 2; mt++)
#pragma unroll
            for (int nt = 0; nt < 3; nt++)
#pragma unroll
                for (int q = 0; q < 4; q++) d[mt][nt][q] = 0.f;

#pragma unroll
        for (int kt = 0; kt < 9; kt++) {
            int slot = kt % 3;
            /* prefetch lin+3 (padding makes overrun safe) */
            uint4 p0 = g_wfrag[WIDX(base + kt + 3, 0)];
            uint4 p1 = g_wfrag[WIDX(base + kt + 3, 1)];
            uint4 p2 = g_wfrag[WIDX(base + kt + 3, 2)];
#pragma unroll
            for (int mt = 0; mt < 2; mt++) {
                mma16816(d[mt][0], AH[mt][kt], buf[slot][0].x, buf[slot][0].y);
                mma16816(d[mt][0], AH[mt][kt], buf[slot][0].z, buf[slot][0].w);
                mma16816(d[mt][1], AH[mt][kt], buf[slot][1].x, buf[slot][1].y);
                mma16816(d[mt][1], AH[mt][kt], buf[slot][1].z, buf[slot][1].w);
                mma16816(d[mt][2], AH[mt][kt], buf[slot][2].x, buf[slot][2].y);
                mma16816(d[mt][2], AH[mt][kt], buf[slot][2].z, buf[slot][2].w);
            }
            buf[slot][0] = p0; buf[slot][1] = p1; buf[slot][2] = p2;
        }

        /* consume */
        const float* bp = b2 + cc * 48;
        if (cc < 58) {
#pragma unroll
            for (int mt = 0; mt < 2; mt++) {
                int er0 = eg * 32 + mt * 16 + gid;
                float cf0 = sCS[er0 * 58 + cc], cf1 = sCS[(er0 + 8) * 58 + cc];
#pragma unroll
                for (int nt = 0; nt < 3; nt++) {
                    int col = cg * 24 + nt * 8 + tig * 2;
                    float b0v = bp[col], b1v = bp[col + 1];
                    acc[mt][nt][0] = fmaf(cf0, d[mt][nt][0] + b0v, acc[mt][nt][0]);
                    acc[mt][nt][1] = fmaf(cf0, d[mt][nt][1] + b1v, acc[mt][nt][1]);
                    acc[mt][nt][2] = fmaf(cf1, d[mt][nt][2] + b0v, acc[mt][nt][2]);
                    acc[mt][nt][3] = fmaf(cf1, d[mt][nt][3] + b1v, acc[mt][nt][3]);
                }
            }
        } else if (cc < 68) {
#pragma unroll
            for (int nt = 0; nt < 3; nt++) {
#pragma unroll
                for (int j = 0; j < 2; j++) {
                    int col = cg * 24 + nt * 8 + tig * 2 + j;
                    int tt = (cc - 58) * 48 + col;
                    int i = tt / 10, o = tt - i * 10;
                    float bb = bp[col];
#pragma unroll
                    for (int mt = 0; mt < 2; mt++) {
                        int er0 = eg * 32 + mt * 16 + gid;
                        atomicAdd(&aP[er0 * 10 + o],
                                  sU[er0 * 48 + i] * (d[mt][nt][j] + bb));
                        atomicAdd(&aP[(er0 + 8) * 10 + o],
                                  sU[(er0 + 8) * 48 + i] * (d[mt][nt][2 + j] + bb));
                    }
                }
            }
        } else {
#pragma unroll
            for (int nt = 0; nt < 3; nt++) {
#pragma unroll
                for (int j = 0; j < 2; j++) {
                    int col = cg * 24 + nt * 8 + tig * 2 + j;
                    int tt = (cc - 68) * 48 + col;
                    if (tt < 100) {
                        int i = tt / 10, o = tt - i * 10;
                        float bb = bp[col];
#pragma unroll
                        for (int mt = 0; mt < 2; mt++) {
                            int er0 = eg * 32 + mt * 16 + gid;
                            float w0 = d[mt][nt][j] + bb;
                            float w1v = d[mt][nt][2 + j] + bb;
                            const float* vp0 = &sV[er0 * 30 + i * 3];
                            const float* vp1 = &sV[(er0 + 8) * 30 + i * 3];
                            atomicAdd(&aQ[er0 * 30 + o * 3],     vp0[0] * w0);
                            atomicAdd(&aQ[er0 * 30 + o * 3 + 1], vp0[1] * w0);
                            atomicAdd(&aQ[er0 * 30 + o * 3 + 2], vp0[2] * w0);
                            atomicAdd(&aQ[(er0 + 8) * 30 + o * 3],     vp1[0] * w1v);
                            atomicAdd(&aQ[(er0 + 8) * 30 + o * 3 + 1], vp1[1] * w1v);
                            atomicAdd(&aQ[(er0 + 8) * 30 + o * 3 + 2], vp1[2] * w1v);
                        }
                    }
                }
            }
        }
    }
    __syncthreads();

    /* scatter out_s fragments */
#pragma unroll
    for (int mt = 0; mt < 2; mt++) {
        int er0 = eg * 32 + mt * 16 + gid;
        int eg0 = e0 + er0, eg1 = eg0 + 8;
        int base0 = sS[er0] * IND, base1 = sS[er0 + 8] * IND;
#pragma unroll
        for (int nt = 0; nt < 3; nt++) {
#pragma unroll
            for (int j = 0; j < 2; j++) {
                int col = cg * 24 + nt * 8 + tig * 2 + j;
                if (eg0 < NE) atomicAdd(&g_sum[base0 + col], acc[mt][nt][j]);
                if (eg1 < NE) atomicAdd(&g_sum[base1 + col], acc[mt][nt][2 + j]);
            }
        }
    }
    /* vector part */
    for (int x = tid; x < EPB * 30; x += 256) {
        int e = x / 30, t = x - e * 30, o = t / 3, ccp = t - o * 3;
        if (e0 + e < NE) {
            float v = s1[e * 3 + ccp] * aP[e * 10 + o] + s0[e] * aQ[e * 30 + t];
            atomicAdd(&g_sum[sS[e] * IND + NS + t], v);
        }
    }
    if (tid < EPB && e0 + tid < NE) atomicAdd(&g_cnt[sS[tid]], 1.f);
}

/* ---------------- epilogue ---------------- */
__global__ void k_zero() {
    int i = blockIdx.x * blockDim.x + threadIdx.x, st = gridDim.x * blockDim.x;
    for (int x = i; x < NN * IND; x += st) g_sum[x] = 0.f;
    for (int x = i; x < NN; x += st) g_cnt[x] = 0.f;
    if (i < 2 * NS + NV) g_stat[i] = 0.f;
}
__global__ void k_pre(const float* __restrict__ na) {
    int i = blockIdx.x * blockDim.x + threadIdx.x, st = gridDim.x * blockDim.x;
    for (int x = i; x < NN * IND; x += st) {
        int n = x / IND;
        g_pre[x] = g_sum[x] / fmaxf(g_cnt[n], 1.f) + na[x];
    }
}
__global__ __launch_bounds__(256) void k_stat() {
    __shared__ float r1[256], r2[256];
    int b = blockIdx.x, tid = threadIdx.x;
    float s = 0.f, q = 0.f;
    if (b < NS) {
        for (int n = tid; n < NN; n += 256) { float v = g_pre[n * IND + b]; s += v; q += v * v; }
    } else {
        int i = b - NS;
        for (int n = tid; n < NN; n += 256) {
            const float* p = &g_pre[n * IND + NS + i * 3];
            s += p[0] * p[0] + p[1] * p[1] + p[2] * p[2];
        }
    }
    r1[tid] = s; r2[tid] = q; __syncthreads();
    for (int o = 128; o > 0; o >>= 1) {
        if (tid < o) { r1[tid] += r1[tid + o]; r2[tid] += r2[tid + o]; }
        __syncthreads();
    }
    if (tid == 0) {
        if (b < NS) { g_stat[b] = r1[0]; g_stat[NS + b] = r2[0]; }
        else g_stat[NS + b] = r1[0];
    }
}
__global__ void k_nrm(const float* __restrict__ bnw, const float* __restrict__ bnb) {
    int t = threadIdx.x;
    if (t < NS) {
        float mu = g_stat[t] * (1.f / NN);
        float var = g_stat[NS + t] * (1.f / NN) - mu * mu;
        float sc = bnw[t] * rsqrtf(var + EPSF);
        g_nrm[t] = sc; g_nrm[NS + t] = bnb[t] - mu * sc;
    } else if (t < NS + NV) {
        int i = t - NS;
        float fn = g_stat[2 * NS + i] * (1.f / (3.f * NN));
        g_nrm[2 * NS + i] = bnw[NS + i] * rsqrtf(fn + EPSF);
    }
}
__global__ void k_apply(float* __restrict__ out) {
    int i = blockIdx.x * blockDim.x + threadIdx.x, st = gridDim.x * blockDim.x;
    for (int x = i; x < NN * IND; x += st) {
        int n = x / IND, d = x - n * IND;
        out[x] = (d < NS) ? g_pre[x] * g_nrm[d] + g_nrm[NS + d]
                          : g_pre[x] * g_nrm[2 * NS + (d - NS) / 3];
    }
}

extern "C" void kernel_launch(void* const* d_in, const int* in_sizes, int n_in,
                              void* d_out, int out_size) {
    (void)in_sizes; (void)n_in; (void)out_size;
    const float* nattr = (const float*)d_in[0];
    const float* ea    = (const float*)d_in[1];
    const float* esh   = (const float*)d_in[2];
    const float* w1    = (const float*)d_in[3];
    const float* b1    = (const float*)d_in[4];
    const float* w2    = (const float*)d_in[5];
    const float* b2    = (const float*)d_in[6];
    const float* bnw   = (const float*)d_in[7];
    const float* bnb   = (const float*)d_in[8];
    const int*   ei    = (const int*)d_in[9];
    float* out = (float*)d_out;

    size_t sm1 = (size_t)(19008 + 20736) * 4;
    cudaFuncSetAttribute(k_fc1,  cudaFuncAttributeMaxDynamicSharedMemorySize, (int)sm1);
    cudaFuncSetAttribute(k_main, cudaFuncAttributeMaxDynamicSharedMemorySize, SMEMTOT);

    k_zero<<<512, 256>>>();
    k_wprep<<<(NLIN * 192 + 255) / 256, 256>>>(w2);
    k_fc1<<<NBLK, 256, sm1>>>(ea, w1, b1);
    k_main<<<NBLK, 256, SMEMTOT>>>(nattr, esh, b2, ei);
    k_pre<<<512, 256>>>(nattr);
    k_stat<<<NS + NV, 256>>>();
    k_nrm<<<1, 64>>>(bnw, bnb);
    k_apply<<<512, 256>>>(out);
}

// round 11
// speedup vs baseline: 1.4720x; 1.4720x over previous
#include <cuda_runtime.h>
#include <cuda_fp16.h>
#include <stdint.h>
#include <math.h>

#define NS 48
#define NV 10
#define NE 100000
#define NN 10000
#define NF 144
#define IND 78
#define WNUM 3364
#define EPB 128
#define NBLK ((NE + EPB - 1) / EPB)
#define NCH 71
#define NTH 384
#define A_SS 0.102062072615966f
#define A_VV 0.223606797749979f
#define ISQ3 0.577350269189626f
#define EPSF 1e-5f

/* ---- SMEM byte offsets (k_main) ---- */
#define OFF_B    0          /* [2 buf][hi 16128 | lo 16128] = 64512 */
#define OFF_BIAS 64512      /* [71][48] f32 = 13632 */
#define OFF_CS   78144      /* [128][58] f32 = 29696 */
#define OFF_U    107840     /* [128][48] f32 = 24576 */
#define OFF_V    132416     /* [128][30] f32 = 15360 */
#define OFF_S0   147776     /* [128] f32 */
#define OFF_S1   148288     /* [128][3] f32 */
#define OFF_SS   149824     /* [128] int */
#define OFF_AP   150336     /* [128][10] f32 */
#define OFF_AQ   155456     /* [128][30] f32 */
#define SMEMTOT  170816

__device__ float g_h[(size_t)NE * NF];
__device__ __half g_whl[(size_t)NCH * NF * 96];  /* per chunk: [144][48hi|48lo] fp16 */
__device__ float g_sum[NN * IND];
__device__ float g_cnt[NN];
__device__ float g_pre[NN * IND];
__device__ float g_stat[2 * NS + NV];
__device__ float g_nrm[2 * NS + NV];

__device__ __forceinline__ uint32_t smem_u32(const void* p) {
    uint32_t a;
    asm("{ .reg .u64 t; cvta.to.shared.u64 t, %1; cvt.u32.u64 %0, t; }" : "=r"(a) : "l"(p));
    return a;
}
__device__ __forceinline__ void ldsm4t(uint32_t* r, uint32_t a) {
    asm volatile("ldmatrix.sync.aligned.m8n8.x4.trans.shared.b16 {%0,%1,%2,%3}, [%4];"
                 : "=r"(r[0]), "=r"(r[1]), "=r"(r[2]), "=r"(r[3]) : "r"(a));
}
__device__ __forceinline__ void mma16816(float* d, const uint32_t* a,
                                         uint32_t b0, uint32_t b1) {
    asm volatile("mma.sync.aligned.m16n8k16.row.col.f32.f16.f16.f32 "
                 "{%0,%1,%2,%3}, {%4,%5,%6,%7}, {%8,%9}, {%0,%1,%2,%3};"
                 : "+f"(d[0]), "+f"(d[1]), "+f"(d[2]), "+f"(d[3])
                 : "r"(a[0]), "r"(a[1]), "r"(a[2]), "r"(a[3]), "r"(b0), "r"(b1));
}
__device__ __forceinline__ void cpa16(uint32_t dst, const void* src) {
    asm volatile("cp.async.cg.shared.global [%0], [%1], 16;" :: "r"(dst), "l"(src));
}
#define CPA_COMMIT() asm volatile("cp.async.commit_group;" ::: "memory")
#define CPA_WAIT0()  asm volatile("cp.async.wait_group 0;" ::: "memory")
__device__ __forceinline__ uint32_t pkh(float x0, float x1) {
    __half h0 = __float2half_rn(x0), h1 = __float2half_rn(x1);
    return (uint32_t)__half_as_ushort(h0) | ((uint32_t)__half_as_ushort(h1) << 16);
}

/* -------- w2 -> fp16 hi/lo chunk blob -------- */
__global__ void k_wprep(const float* __restrict__ w2) {
    int x = blockIdx.x * blockDim.x + threadIdx.x;
    if (x < NCH * NF * 48) {
        int n = x % 48, t = x / 48, k = t % NF, ch = t / NF;
        int gc = ch * 48 + n;
        float v = (gc < WNUM) ? w2[(size_t)k * WNUM + gc] : 0.f;
        __half hb = __float2half_rn(v);
        __half lb = __float2half_rn(v - __half2float(hb));
        size_t base = (size_t)(ch * NF + k) * 96;
        g_whl[base + n] = hb;
        g_whl[base + 48 + n] = lb;
    }
}

/* ---------------- fc1 + relu -> g_h (FFMA fp32) ---------------- */
__global__ __launch_bounds__(256, 1) void k_fc1(const float* __restrict__ ea,
                                                const float* __restrict__ w1,
                                                const float* __restrict__ b1) {
    extern __shared__ float sm[];
    float* sE = sm;            /* [144][132] */
    float* sW = sm + 19008;    /* [144][144] */
    int tid = threadIdx.x, tx = tid & 7, ty = tid >> 3;
    int e0 = blockIdx.x * EPB;

    for (int x = tid; x < EPB * NF; x += 256) {
        int e = x / NF, k = x - e * NF;
        sE[k * 132 + e] = (e0 + e < NE) ? ea[(size_t)(e0 + e) * NF + k] : 0.f;
    }
    for (int x = tid; x < NF * NF; x += 256) sW[x] = w1[x];
    __syncthreads();

    float acc[4][18];
#pragma unroll
    for (int r = 0; r < 4; r++)
#pragma unroll
        for (int j = 0; j < 18; j++) acc[r][j] = 0.f;

    for (int k = 0; k < NF; k++) {
        float4 hv = *(const float4*)&sE[k * 132 + ty * 4];
        float wv[18];
#pragma unroll
        for (int j = 0; j < 18; j++) wv[j] = sW[k * NF + tx * 18 + j];
#pragma unroll
        for (int j = 0; j < 18; j++) {
            acc[0][j] = fmaf(hv.x, wv[j], acc[0][j]);
            acc[1][j] = fmaf(hv.y, wv[j], acc[1][j]);
            acc[2][j] = fmaf(hv.z, wv[j], acc[2][j]);
            acc[3][j] = fmaf(hv.w, wv[j], acc[3][j]);
        }
    }
#pragma unroll
    for (int r = 0; r < 4; r++) {
        int e = e0 + ty * 4 + r;
        if (e < NE) {
#pragma unroll
            for (int j = 0; j < 18; j++) {
                int o = tx * 18 + j;
                g_h[(size_t)e * NF + o] = fmaxf(acc[r][j] + b1[o], 0.f);
            }
        }
    }
}

/* -------- fused fc2: fp16 mma 2-product, 12 warps, cp.async B -------- */
__global__ __launch_bounds__(NTH, 1) void k_main(const float* __restrict__ na,
                                                 const float* __restrict__ esh,
                                                 const float* __restrict__ b2,
                                                 const int* __restrict__ ei) {
    extern __shared__ char smc[];
    uint32_t smb = smem_u32(smc);
    float* sBias = (float*)(smc + OFF_BIAS);
    float* sCS = (float*)(smc + OFF_CS);
    float* sU  = (float*)(smc + OFF_U);
    float* sV  = (float*)(smc + OFF_V);
    float* s0  = (float*)(smc + OFF_S0);
    float* s1  = (float*)(smc + OFF_S1);
    int*   sS  = (int*)(smc + OFF_SS);
    float* aP  = (float*)(smc + OFF_AP);
    float* aQ  = (float*)(smc + OFF_AQ);

    int tid = threadIdx.x, lane = tid & 31, warp = tid >> 5;
    int gid = lane >> 2, tig = lane & 3;
    int eg = warp / 3, cg = warp % 3;     /* eg: 32 edges, cg: 16 cols */
    int e0 = blockIdx.x * EPB;

    /* smem prep */
    for (int x = tid; x < EPB * IND; x += NTH) {
        int e = x / IND, d = x - e * IND;
        float v = 0.f;
        if (e0 + e < NE) { int dst = ei[NE + e0 + e]; v = na[dst * IND + d]; }
        if (d < NS) sU[e * NS + d] = A_SS * v;
        else        sV[e * 30 + d - NS] = A_VV * v;
    }
    if (tid < EPB) {
        int egl = e0 + tid;
        if (egl < NE) {
            sS[tid] = ei[egl]; s0[tid] = esh[egl * 4];
            s1[tid * 3] = esh[egl * 4 + 1]; s1[tid * 3 + 1] = esh[egl * 4 + 2];
            s1[tid * 3 + 2] = esh[egl * 4 + 3];
        } else {
            sS[tid] = 0; s0[tid] = 0.f;
            s1[tid * 3] = s1[tid * 3 + 1] = s1[tid * 3 + 2] = 0.f;
        }
    }
    for (int x = tid; x < EPB * 40; x += NTH) aP[x] = 0.f;  /* aP,aQ contiguous */
    for (int x = tid; x < NCH * 48; x += NTH)
        sBias[x] = (x < WNUM) ? b2[x] : 0.f;
    __syncthreads();
    for (int x = tid; x < EPB * 58; x += NTH) {
        int e = x / 58, i = x - e * 58;
        if (i < 48) sCS[x] = s0[e] * sU[e * 48 + i];
        else {
            int ii = i - 48;
            sCS[x] = ISQ3 * (sV[e * 30 + ii * 3] * s1[e * 3] +
                             sV[e * 30 + ii * 3 + 1] * s1[e * 3 + 1] +
                             sV[e * 30 + ii * 3 + 2] * s1[e * 3 + 2]);
        }
    }

    /* A fragments in registers, chunk-invariant, fp16 */
    uint32_t AH[2][9][4];
#pragma unroll
    for (int mt = 0; mt < 2; mt++) {
        int r0 = eg * 32 + mt * 16 + gid;
#pragma unroll
        for (int kt = 0; kt < 9; kt++) {
#pragma unroll
            for (int q = 0; q < 4; q++) {
                int row = r0 + (q & 1) * 8;
                int k = kt * 16 + tig * 2 + (q >> 1) * 8;
                float f0 = 0.f, f1 = 0.f;
                if (e0 + row < NE) {
                    const float* p = &g_h[(size_t)(e0 + row) * NF + k];
                    f0 = p[0]; f1 = p[1];
                }
                AH[mt][kt][q] = pkh(f0, f1);
            }
        }
    }

    /* B ldmatrix address: cg owns cols [cg*16, cg*16+16) -> +cg*32 bytes */
    uint32_t a4 = smb + OFF_B + cg * 32 + (lane & 15) * 112 + (lane >> 4) * 16;

    float acc[2][2][4];
#pragma unroll
    for (int mt = 0; mt < 2; mt++)
#pragma unroll
        for (int nt = 0; nt < 2; nt++)
#pragma unroll
            for (int q = 0; q < 4; q++) acc[mt][nt][q] = 0.f;

    /* prologue fill chunk 0 */
    {
        const char* src = (const char*)g_whl;
        for (int x = tid; x < 1728; x += NTH) {
            int k = x / 12, part = x - k * 12;
            uint32_t dst = smb + OFF_B + (part < 6 ? 0 : 16128) + k * 112 + (part % 6) * 16;
            cpa16(dst, src + k * 192 + part * 16);
        }
        CPA_COMMIT();
    }

    for (int cc = 0; cc < NCH; cc++) {
        int buf = cc & 1;
        CPA_WAIT0();
        __syncthreads();   /* B(cc) visible; other buf's reads done */
        if (cc + 1 < NCH) {
            const char* src = (const char*)g_whl + (size_t)(cc + 1) * 27648;
            uint32_t dstb = smb + OFF_B + (buf ^ 1) * 32256;
            for (int x = tid; x < 1728; x += NTH) {
                int k = x / 12, part = x - k * 12;
                cpa16(dstb + (part < 6 ? 0 : 16128) + k * 112 + (part % 6) * 16,
                      (const char*)src + k * 192 + part * 16);
            }
            CPA_COMMIT();
        }

        float d[2][2][4];
#pragma unroll
        for (int mt = 0; mt < 2; mt++)
#pragma unroll
            for (int nt = 0; nt < 2; nt++)
#pragma unroll
                for (int q = 0; q < 4; q++) d[mt][nt][q] = 0.f;

        uint32_t bofs = buf * 32256;
        uint32_t bh[4], bl[4];
        ldsm4t(bh, a4 + bofs);
        ldsm4t(bl, a4 + bofs + 16128);
#pragma unroll
        for (int kt = 0; kt < 9; kt++) {
            uint32_t nh[4], nl[4];
            if (kt < 8) {
                ldsm4t(nh, a4 + bofs + (kt + 1) * 1792);
                ldsm4t(nl, a4 + bofs + 16128 + (kt + 1) * 1792);
            }
#pragma unroll
            for (int mt = 0; mt < 2; mt++) {
                mma16816(d[mt][0], AH[mt][kt], bh[0], bh[1]);
                mma16816(d[mt][0], AH[mt][kt], bl[0], bl[1]);
                mma16816(d[mt][1], AH[mt][kt], bh[2], bh[3]);
                mma16816(d[mt][1], AH[mt][kt], bl[2], bl[3]);
            }
            if (kt < 8) {
#pragma unroll
                for (int q = 0; q < 4; q++) { bh[q] = nh[q]; bl[q] = nl[q]; }
            }
        }

        /* consume */
        const float* bp = sBias + cc * 48;
        if (cc < 58) {
#pragma unroll
            for (int mt = 0; mt < 2; mt++) {
                int er0 = eg * 32 + mt * 16 + gid;
                float cf0 = sCS[er0 * 58 + cc], cf1 = sCS[(er0 + 8) * 58 + cc];
#pragma unroll
                for (int nt = 0; nt < 2; nt++) {
                    int col = cg * 16 + nt * 8 + tig * 2;
                    float b0v = bp[col], b1v = bp[col + 1];
                    acc[mt][nt][0] = fmaf(cf0, d[mt][nt][0] + b0v, acc[mt][nt][0]);
                    acc[mt][nt][1] = fmaf(cf0, d[mt][nt][1] + b1v, acc[mt][nt][1]);
                    acc[mt][nt][2] = fmaf(cf1, d[mt][nt][2] + b0v, acc[mt][nt][2]);
                    acc[mt][nt][3] = fmaf(cf1, d[mt][nt][3] + b1v, acc[mt][nt][3]);
                }
            }
        } else if (cc < 68) {
#pragma unroll
            for (int nt = 0; nt < 2; nt++) {
#pragma unroll
                for (int j = 0; j < 2; j++) {
                    int col = cg * 16 + nt * 8 + tig * 2 + j;
                    int tt = (cc - 58) * 48 + col;
                    int i = tt / 10, o = tt - i * 10;
                    float bb = bp[col];
#pragma unroll
                    for (int mt = 0; mt < 2; mt++) {
                        int er0 = eg * 32 + mt * 16 + gid;
                        atomicAdd(&aP[er0 * 10 + o],
                                  sU[er0 * 48 + i] * (d[mt][nt][j] + bb));
                        atomicAdd(&aP[(er0 + 8) * 10 + o],
                                  sU[(er0 + 8) * 48 + i] * (d[mt][nt][2 + j] + bb));
                    }
                }
            }
        } else {
#pragma unroll
            for (int nt = 0; nt < 2; nt++) {
#pragma unroll
                for (int j = 0; j < 2; j++) {
                    int col = cg * 16 + nt * 8 + tig * 2 + j;
                    int tt = (cc - 68) * 48 + col;
                    if (tt < 100) {
                        int i = tt / 10, o = tt - i * 10;
                        float bb = bp[col];
#pragma unroll
                        for (int mt = 0; mt < 2; mt++) {
                            int er0 = eg * 32 + mt * 16 + gid;
                            float w0 = d[mt][nt][j] + bb;
                            float w1v = d[mt][nt][2 + j] + bb;
                            const float* vp0 = &sV[er0 * 30 + i * 3];
                            const float* vp1 = &sV[(er0 + 8) * 30 + i * 3];
                            atomicAdd(&aQ[er0 * 30 + o * 3],     vp0[0] * w0);
                            atomicAdd(&aQ[er0 * 30 + o * 3 + 1], vp0[1] * w0);
                            atomicAdd(&aQ[er0 * 30 + o * 3 + 2], vp0[2] * w0);
                            atomicAdd(&aQ[(er0 + 8) * 30 + o * 3],     vp1[0] * w1v);
                            atomicAdd(&aQ[(er0 + 8) * 30 + o * 3 + 1], vp1[1] * w1v);
                            atomicAdd(&aQ[(er0 + 8) * 30 + o * 3 + 2], vp1[2] * w1v);
                        }
                    }
                }
            }
        }
    }
    __syncthreads();

    /* scatter out_s fragments */
#pragma unroll
    for (int mt = 0; mt < 2; mt++) {
        int er0 = eg * 32 + mt * 16 + gid;
        int eg0 = e0 + er0, eg1 = eg0 + 8;
        int base0 = sS[er0] * IND, base1 = sS[er0 + 8] * IND;
#pragma unroll
        for (int nt = 0; nt < 2; nt++) {
#pragma unroll
            for (int j = 0; j < 2; j++) {
                int col = cg * 16 + nt * 8 + tig * 2 + j;
                if (eg0 < NE) atomicAdd(&g_sum[base0 + col], acc[mt][nt][j]);
                if (eg1 < NE) atomicAdd(&g_sum[base1 + col], acc[mt][nt][2 + j]);
            }
        }
    }
    /* vector part */
    for (int x = tid; x < EPB * 30; x += NTH) {
        int e = x / 30, t = x - e * 30, o = t / 3, ccp = t - o * 3;
        if (e0 + e < NE) {
            float v = s1[e * 3 + ccp] * aP[e * 10 + o] + s0[e] * aQ[e * 30 + t];
            atomicAdd(&g_sum[sS[e] * IND + NS + t], v);
        }
    }
    if (tid < EPB && e0 + tid < NE) atomicAdd(&g_cnt[sS[tid]], 1.f);
}

/* ---------------- epilogue ---------------- */
__global__ void k_zero() {
    int i = blockIdx.x * blockDim.x + threadIdx.x, st = gridDim.x * blockDim.x;
    for (int x = i; x < NN * IND; x += st) g_sum[x] = 0.f;
    for (int x = i; x < NN; x += st) g_cnt[x] = 0.f;
    if (i < 2 * NS + NV) g_stat[i] = 0.f;
}
__global__ void k_pre(const float* __restrict__ na) {
    int i = blockIdx.x * blockDim.x + threadIdx.x, st = gridDim.x * blockDim.x;
    for (int x = i; x < NN * IND; x += st) {
        int n = x / IND;
        g_pre[x] = g_sum[x] / fmaxf(g_cnt[n], 1.f) + na[x];
    }
}
__global__ __launch_bounds__(256) void k_stat() {
    __shared__ float r1[256], r2[256];
    int b = blockIdx.x, tid = threadIdx.x;
    float s = 0.f, q = 0.f;
    if (b < NS) {
        for (int n = tid; n < NN; n += 256) { float v = g_pre[n * IND + b]; s += v; q += v * v; }
    } else {
        int i = b - NS;
        for (int n = tid; n < NN; n += 256) {
            const float* p = &g_pre[n * IND + NS + i * 3];
            s += p[0] * p[0] + p[1] * p[1] + p[2] * p[2];
        }
    }
    r1[tid] = s; r2[tid] = q; __syncthreads();
    for (int o = 128; o > 0; o >>= 1) {
        if (tid < o) { r1[tid] += r1[tid + o]; r2[tid] += r2[tid + o]; }
        __syncthreads();
    }
    if (tid == 0) {
        if (b < NS) { g_stat[b] = r1[0]; g_stat[NS + b] = r2[0]; }
        else g_stat[NS + b] = r1[0];
    }
}
__global__ void k_nrm(const float* __restrict__ bnw, const float* __restrict__ bnb) {
    int t = threadIdx.x;
    if (t < NS) {
        float mu = g_stat[t] * (1.f / NN);
        float var = g_stat[NS + t] * (1.f / NN) - mu * mu;
        float sc = bnw[t] * rsqrtf(var + EPSF);
        g_nrm[t] = sc; g_nrm[NS + t] = bnb[t] - mu * sc;
    } else if (t < NS + NV) {
        int i = t - NS;
        float fn = g_stat[2 * NS + i] * (1.f / (3.f * NN));
        g_nrm[2 * NS + i] = bnw[NS + i] * rsqrtf(fn + EPSF);
    }
}
__global__ void k_apply(float* __restrict__ out) {
    int i = blockIdx.x * blockDim.x + threadIdx.x, st = gridDim.x * blockDim.x;
    for (int x = i; x < NN * IND; x += st) {
        int n = x / IND, d = x - n * IND;
        out[x] = (d < NS) ? g_pre[x] * g_nrm[d] + g_nrm[NS + d]
                          : g_pre[x] * g_nrm[2 * NS + (d - NS) / 3];
    }
}

extern "C" void kernel_launch(void* const* d_in, const int* in_sizes, int n_in,
                              void* d_out, int out_size) {
    (void)in_sizes; (void)n_in; (void)out_size;
    const float* nattr = (const float*)d_in[0];
    const float* ea    = (const float*)d_in[1];
    const float* esh   = (const float*)d_in[2];
    const float* w1    = (const float*)d_in[3];
    const float* b1    = (const float*)d_in[4];
    const float* w2    = (const float*)d_in[5];
    const float* b2    = (const float*)d_in[6];
    const float* bnw   = (const float*)d_in[7];
    const float* bnb   = (const float*)d_in[8];
    const int*   ei    = (const int*)d_in[9];
    float* out = (float*)d_out;

    size_t sm1 = (size_t)(19008 + 20736) * 4;
    cudaFuncSetAttribute(k_fc1,  cudaFuncAttributeMaxDynamicSharedMemorySize, (int)sm1);
    cudaFuncSetAttribute(k_main, cudaFuncAttributeMaxDynamicSharedMemorySize, SMEMTOT);

    k_zero<<<512, 256>>>();
    k_wprep<<<(NCH * NF * 48 + 255) / 256, 256>>>(w2);
    k_fc1<<<NBLK, 256, sm1>>>(ea, w1, b1);
    k_main<<<NBLK, NTH, SMEMTOT>>>(nattr, esh, b2, ei);
    k_pre<<<512, 256>>>(nattr);
    k_stat<<<NS + NV, 256>>>();
    k_nrm<<<1, 64>>>(bnw, bnb);
    k_apply<<<512, 256>>>(out);
}

// round 12
// speedup vs baseline: 1.9433x; 1.3201x over previous
#include <cuda_runtime.h>
#include <cuda_fp16.h>
#include <stdint.h>
#include <math.h>

#define NS 48
#define NV 10
#define NE 100000
#define NN 10000
#define NF 144
#define IND 78
#define WNUM 3364
#define EPB 128
#define NBLK ((NE + EPB - 1) / EPB)
#define NCH 71
#define NTH 384
#define A_SS 0.102062072615966f
#define A_VV 0.223606797749979f
#define ISQ3 0.577350269189626f
#define EPSF 1e-5f

/* ---- SMEM byte offsets (k_main) ---- */
#define OFF_B    0          /* [2 buf][16128] = 32256 */
#define OFF_BIAS 32256      /* [71][48] f32 = 13632 */
#define OFF_CS   45888      /* [128][58] f32 = 29696 */
#define OFF_U    75584      /* [128][48] f32 = 24576 */
#define OFF_V    100160     /* [128][30] f32 = 15360 */
#define OFF_S0   115520     /* [128] f32 */
#define OFF_S1   116032     /* [128][3] f32 */
#define OFF_SS   117568     /* [128] int */
#define OFF_AP   118080     /* [128][10] f32 */
#define OFF_AQ   123200     /* [128][30] f32 */
#define SMEMTOT  138560

__device__ float g_h[(size_t)NE * NF];
__device__ __half g_whl[(size_t)NCH * NF * 48];  /* per chunk: [144][48] fp16 */
__device__ float g_sum[NN * IND];
__device__ float g_cnt[NN];
__device__ float g_pre[NN * IND];
__device__ float g_stat[2 * NS + NV];
__device__ float g_nrm[2 * NS + NV];

__device__ __forceinline__ uint32_t smem_u32(const void* p) {
    uint32_t a;
    asm("{ .reg .u64 t; cvta.to.shared.u64 t, %1; cvt.u32.u64 %0, t; }" : "=r"(a) : "l"(p));
    return a;
}
__device__ __forceinline__ void ldsm4t(uint32_t* r, uint32_t a) {
    asm volatile("ldmatrix.sync.aligned.m8n8.x4.trans.shared.b16 {%0,%1,%2,%3}, [%4];"
                 : "=r"(r[0]), "=r"(r[1]), "=r"(r[2]), "=r"(r[3]) : "r"(a));
}
__device__ __forceinline__ void mma16816(float* d, const uint32_t* a,
                                         uint32_t b0, uint32_t b1) {
    asm volatile("mma.sync.aligned.m16n8k16.row.col.f32.f16.f16.f32 "
                 "{%0,%1,%2,%3}, {%4,%5,%6,%7}, {%8,%9}, {%0,%1,%2,%3};"
                 : "+f"(d[0]), "+f"(d[1]), "+f"(d[2]), "+f"(d[3])
                 : "r"(a[0]), "r"(a[1]), "r"(a[2]), "r"(a[3]), "r"(b0), "r"(b1));
}
__device__ __forceinline__ void cpa16(uint32_t dst, const void* src) {
    asm volatile("cp.async.cg.shared.global [%0], [%1], 16;" :: "r"(dst), "l"(src));
}
#define CPA_COMMIT() asm volatile("cp.async.commit_group;" ::: "memory")
#define CPA_WAIT0()  asm volatile("cp.async.wait_group 0;" ::: "memory")
__device__ __forceinline__ uint32_t pkh(float x0, float x1) {
    __half h0 = __float2half_rn(x0), h1 = __float2half_rn(x1);
    return (uint32_t)__half_as_ushort(h0) | ((uint32_t)__half_as_ushort(h1) << 16);
}

/* -------- w2 -> fp16 chunk blob -------- */
__global__ void k_wprep(const float* __restrict__ w2) {
    int x = blockIdx.x * blockDim.x + threadIdx.x;
    if (x < NCH * NF * 48) {
        int n = x % 48, t = x / 48, k = t % NF, ch = t / NF;
        int gc = ch * 48 + n;
        float v = (gc < WNUM) ? w2[(size_t)k * WNUM + gc] : 0.f;
        g_whl[(size_t)(ch * NF + k) * 48 + n] = __float2half_rn(v);
    }
}

/* ---------------- fc1 + relu -> g_h (FFMA fp32) ---------------- */
__global__ __launch_bounds__(256, 1) void k_fc1(const float* __restrict__ ea,
                                                const float* __restrict__ w1,
                                                const float* __restrict__ b1) {
    extern __shared__ float sm[];
    float* sE = sm;            /* [144][132] */
    float* sW = sm + 19008;    /* [144][144] */
    int tid = threadIdx.x, tx = tid & 7, ty = tid >> 3;
    int e0 = blockIdx.x * EPB;

    for (int x = tid; x < EPB * NF; x += 256) {
        int e = x / NF, k = x - e * NF;
        sE[k * 132 + e] = (e0 + e < NE) ? ea[(size_t)(e0 + e) * NF + k] : 0.f;
    }
    for (int x = tid; x < NF * NF; x += 256) sW[x] = w1[x];
    __syncthreads();

    float acc[4][18];
#pragma unroll
    for (int r = 0; r < 4; r++)
#pragma unroll
        for (int j = 0; j < 18; j++) acc[r][j] = 0.f;

    for (int k = 0; k < NF; k++) {
        float4 hv = *(const float4*)&sE[k * 132 + ty * 4];
        float wv[18];
#pragma unroll
        for (int j = 0; j < 18; j++) wv[j] = sW[k * NF + tx * 18 + j];
#pragma unroll
        for (int j = 0; j < 18; j++) {
            acc[0][j] = fmaf(hv.x, wv[j], acc[0][j]);
            acc[1][j] = fmaf(hv.y, wv[j], acc[1][j]);
            acc[2][j] = fmaf(hv.z, wv[j], acc[2][j]);
            acc[3][j] = fmaf(hv.w, wv[j], acc[3][j]);
        }
    }
#pragma unroll
    for (int r = 0; r < 4; r++) {
        int e = e0 + ty * 4 + r;
        if (e < NE) {
#pragma unroll
            for (int j = 0; j < 18; j++) {
                int o = tx * 18 + j;
                g_h[(size_t)e * NF + o] = fmaxf(acc[r][j] + b1[o], 0.f);
            }
        }
    }
}

/* -------- fused fc2: fp16 mma single-product, 12 warps, cp.async B -------- */
__global__ __launch_bounds__(NTH, 1) void k_main(const float* __restrict__ na,
                                                 const float* __restrict__ esh,
                                                 const float* __restrict__ b2,
                                                 const int* __restrict__ ei) {
    extern __shared__ char smc[];
    uint32_t smb = smem_u32(smc);
    float* sBias = (float*)(smc + OFF_BIAS);
    float* sCS = (float*)(smc + OFF_CS);
    float* sU  = (float*)(smc + OFF_U);
    float* sV  = (float*)(smc + OFF_V);
    float* s0  = (float*)(smc + OFF_S0);
    float* s1  = (float*)(smc + OFF_S1);
    int*   sS  = (int*)(smc + OFF_SS);
    float* aP  = (float*)(smc + OFF_AP);
    float* aQ  = (float*)(smc + OFF_AQ);

    int tid = threadIdx.x, lane = tid & 31, warp = tid >> 5;
    int gid = lane >> 2, tig = lane & 3;
    int eg = warp / 3, cg = warp % 3;     /* eg: 32 edges, cg: 16 cols */
    int e0 = blockIdx.x * EPB;

    /* smem prep */
    for (int x = tid; x < EPB * IND; x += NTH) {
        int e = x / IND, d = x - e * IND;
        float v = 0.f;
        if (e0 + e < NE) { int dst = ei[NE + e0 + e]; v = na[dst * IND + d]; }
        if (d < NS) sU[e * NS + d] = A_SS * v;
        else        sV[e * 30 + d - NS] = A_VV * v;
    }
    if (tid < EPB) {
        int egl = e0 + tid;
        if (egl < NE) {
            sS[tid] = ei[egl]; s0[tid] = esh[egl * 4];
            s1[tid * 3] = esh[egl * 4 + 1]; s1[tid * 3 + 1] = esh[egl * 4 + 2];
            s1[tid * 3 + 2] = esh[egl * 4 + 3];
        } else {
            sS[tid] = 0; s0[tid] = 0.f;
            s1[tid * 3] = s1[tid * 3 + 1] = s1[tid * 3 + 2] = 0.f;
        }
    }
    for (int x = tid; x < EPB * 40; x += NTH) aP[x] = 0.f;  /* aP,aQ contiguous */
    for (int x = tid; x < NCH * 48; x += NTH)
        sBias[x] = (x < WNUM) ? b2[x] : 0.f;
    __syncthreads();
    for (int x = tid; x < EPB * 58; x += NTH) {
        int e = x / 58, i = x - e * 58;
        if (i < 48) sCS[x] = s0[e] * sU[e * 48 + i];
        else {
            int ii = i - 48;
            sCS[x] = ISQ3 * (sV[e * 30 + ii * 3] * s1[e * 3] +
                             sV[e * 30 + ii * 3 + 1] * s1[e * 3 + 1] +
                             sV[e * 30 + ii * 3 + 2] * s1[e * 3 + 2]);
        }
    }

    /* A fragments in registers, chunk-invariant, fp16 */
    uint32_t AH[2][9][4];
#pragma unroll
    for (int mt = 0; mt < 2; mt++) {
        int r0 = eg * 32 + mt * 16 + gid;
#pragma unroll
        for (int kt = 0; kt < 9; kt++) {
#pragma unroll
            for (int q = 0; q < 4; q++) {
                int row = r0 + (q & 1) * 8;
                int k = kt * 16 + tig * 2 + (q >> 1) * 8;
                float f0 = 0.f, f1 = 0.f;
                if (e0 + row < NE) {
                    const float* p = &g_h[(size_t)(e0 + row) * NF + k];
                    f0 = p[0]; f1 = p[1];
                }
                AH[mt][kt][q] = pkh(f0, f1);
            }
        }
    }

    /* B ldmatrix address: cg owns cols [cg*16, cg*16+16) -> +cg*32 bytes */
    uint32_t a4 = smb + OFF_B + cg * 32 + (lane & 15) * 112 + (lane >> 4) * 16;

    float acc[2][2][4];
#pragma unroll
    for (int mt = 0; mt < 2; mt++)
#pragma unroll
        for (int nt = 0; nt < 2; nt++)
#pragma unroll
            for (int q = 0; q < 4; q++) acc[mt][nt][q] = 0.f;

    /* prologue fill chunk 0: 144 rows x 96 bytes = 864 x 16B */
    {
        const char* src = (const char*)g_whl;
        for (int x = tid; x < 864; x += NTH) {
            int k = x / 6, part = x - k * 6;
            cpa16(smb + OFF_B + k * 112 + part * 16, src + k * 96 + part * 16);
        }
        CPA_COMMIT();
    }

    for (int cc = 0; cc < NCH; cc++) {
        int buf = cc & 1;
        CPA_WAIT0();
        __syncthreads();   /* B(cc) visible; other buf's reads done */
        if (cc + 1 < NCH) {
            const char* src = (const char*)g_whl + (size_t)(cc + 1) * 13824;
            uint32_t dstb = smb + OFF_B + (buf ^ 1) * 16128;
            for (int x = tid; x < 864; x += NTH) {
                int k = x / 6, part = x - k * 6;
                cpa16(dstb + k * 112 + part * 16, src + k * 96 + part * 16);
            }
            CPA_COMMIT();
        }

        float d[2][2][4];
#pragma unroll
        for (int mt = 0; mt < 2; mt++)
#pragma unroll
            for (int nt = 0; nt < 2; nt++)
#pragma unroll
                for (int q = 0; q < 4; q++) d[mt][nt][q] = 0.f;

        uint32_t bofs = buf * 16128;
        uint32_t bh[4];
        ldsm4t(bh, a4 + bofs);
#pragma unroll
        for (int kt = 0; kt < 9; kt++) {
            uint32_t nh[4];
            if (kt < 8) ldsm4t(nh, a4 + bofs + (kt + 1) * 1792);
#pragma unroll
            for (int mt = 0; mt < 2; mt++) {
                mma16816(d[mt][0], AH[mt][kt], bh[0], bh[1]);
                mma16816(d[mt][1], AH[mt][kt], bh[2], bh[3]);
            }
            if (kt < 8) {
#pragma unroll
                for (int q = 0; q < 4; q++) bh[q] = nh[q];
            }
        }

        /* consume */
        const float* bp = sBias + cc * 48;
        if (cc < 58) {
#pragma unroll
            for (int mt = 0; mt < 2; mt++) {
                int er0 = eg * 32 + mt * 16 + gid;
                float cf0 = sCS[er0 * 58 + cc], cf1 = sCS[(er0 + 8) * 58 + cc];
#pragma unroll
                for (int nt = 0; nt < 2; nt++) {
                    int col = cg * 16 + nt * 8 + tig * 2;
                    float b0v = bp[col], b1v = bp[col + 1];
                    acc[mt][nt][0] = fmaf(cf0, d[mt][nt][0] + b0v, acc[mt][nt][0]);
                    acc[mt][nt][1] = fmaf(cf0, d[mt][nt][1] + b1v, acc[mt][nt][1]);
                    acc[mt][nt][2] = fmaf(cf1, d[mt][nt][2] + b0v, acc[mt][nt][2]);
                    acc[mt][nt][3] = fmaf(cf1, d[mt][nt][3] + b1v, acc[mt][nt][3]);
                }
            }
        } else if (cc < 68) {
#pragma unroll
            for (int nt = 0; nt < 2; nt++) {
#pragma unroll
                for (int j = 0; j < 2; j++) {
                    int col = cg * 16 + nt * 8 + tig * 2 + j;
                    int tt = (cc - 58) * 48 + col;
                    int i = tt / 10, o = tt - i * 10;
                    float bb = bp[col];
#pragma unroll
                    for (int mt = 0; mt < 2; mt++) {
                        int er0 = eg * 32 + mt * 16 + gid;
                        atomicAdd(&aP[er0 * 10 + o],
                                  sU[er0 * 48 + i] * (d[mt][nt][j] + bb));
                        atomicAdd(&aP[(er0 + 8) * 10 + o],
                                  sU[(er0 + 8) * 48 + i] * (d[mt][nt][2 + j] + bb));
                    }
                }
            }
        } else {
#pragma unroll
            for (int nt = 0; nt < 2; nt++) {
#pragma unroll
                for (int j = 0; j < 2; j++) {
                    int col = cg * 16 + nt * 8 + tig * 2 + j;
                    int tt = (cc - 68) * 48 + col;
                    if (tt < 100) {
                        int i = tt / 10, o = tt - i * 10;
                        float bb = bp[col];
#pragma unroll
                        for (int mt = 0; mt < 2; mt++) {
                            int er0 = eg * 32 + mt * 16 + gid;
                            float w0 = d[mt][nt][j] + bb;
                            float w1v = d[mt][nt][2 + j] + bb;
                            const float* vp0 = &sV[er0 * 30 + i * 3];
                            const float* vp1 = &sV[(er0 + 8) * 30 + i * 3];
                            atomicAdd(&aQ[er0 * 30 + o * 3],     vp0[0] * w0);
                            atomicAdd(&aQ[er0 * 30 + o * 3 + 1], vp0[1] * w0);
                            atomicAdd(&aQ[er0 * 30 + o * 3 + 2], vp0[2] * w0);
                            atomicAdd(&aQ[(er0 + 8) * 30 + o * 3],     vp1[0] * w1v);
                            atomicAdd(&aQ[(er0 + 8) * 30 + o * 3 + 1], vp1[1] * w1v);
                            atomicAdd(&aQ[(er0 + 8) * 30 + o * 3 + 2], vp1[2] * w1v);
                        }
                    }
                }
            }
        }
    }
    __syncthreads();

    /* scatter out_s fragments */
#pragma unroll
    for (int mt = 0; mt < 2; mt++) {
        int er0 = eg * 32 + mt * 16 + gid;
        int eg0 = e0 + er0, eg1 = eg0 + 8;
        int base0 = sS[er0] * IND, base1 = sS[er0 + 8] * IND;
#pragma unroll
        for (int nt = 0; nt < 2; nt++) {
#pragma unroll
            for (int j = 0; j < 2; j++) {
                int col = cg * 16 + nt * 8 + tig * 2 + j;
                if (eg0 < NE) atomicAdd(&g_sum[base0 + col], acc[mt][nt][j]);
                if (eg1 < NE) atomicAdd(&g_sum[base1 + col], acc[mt][nt][2 + j]);
            }
        }
    }
    /* vector part */
    for (int x = tid; x < EPB * 30; x += NTH) {
        int e = x / 30, t = x - e * 30, o = t / 3, ccp = t - o * 3;
        if (e0 + e < NE) {
            float v = s1[e * 3 + ccp] * aP[e * 10 + o] + s0[e] * aQ[e * 30 + t];
            atomicAdd(&g_sum[sS[e] * IND + NS + t], v);
        }
    }
    if (tid < EPB && e0 + tid < NE) atomicAdd(&g_cnt[sS[tid]], 1.f);
}

/* ---------------- epilogue ---------------- */
__global__ void k_zero() {
    int i = blockIdx.x * blockDim.x + threadIdx.x, st = gridDim.x * blockDim.x;
    for (int x = i; x < NN * IND; x += st) g_sum[x] = 0.f;
    for (int x = i; x < NN; x += st) g_cnt[x] = 0.f;
    if (i < 2 * NS + NV) g_stat[i] = 0.f;
}
__global__ void k_pre(const float* __restrict__ na) {
    int i = blockIdx.x * blockDim.x + threadIdx.x, st = gridDim.x * blockDim.x;
    for (int x = i; x < NN * IND; x += st) {
        int n = x / IND;
        g_pre[x] = g_sum[x] / fmaxf(g_cnt[n], 1.f) + na[x];
    }
}
__global__ __launch_bounds__(256) void k_stat() {
    __shared__ float r1[256], r2[256];
    int b = blockIdx.x, tid = threadIdx.x;
    float s = 0.f, q = 0.f;
    if (b < NS) {
        for (int n = tid; n < NN; n += 256) { float v = g_pre[n * IND + b]; s += v; q += v * v; }
    } else {
        int i = b - NS;
        for (int n = tid; n < NN; n += 256) {
            const float* p = &g_pre[n * IND + NS + i * 3];
            s += p[0] * p[0] + p[1] * p[1] + p[2] * p[2];
        }
    }
    r1[tid] = s; r2[tid] = q; __syncthreads();
    for (int o = 128; o > 0; o >>= 1) {
        if (tid < o) { r1[tid] += r1[tid + o]; r2[tid] += r2[tid + o]; }
        __syncthreads();
    }
    if (tid == 0) {
        if (b < NS) { g_stat[b] = r1[0]; g_stat[NS + b] = r2[0]; }
        else g_stat[NS + b] = r1[0];
    }
}
__global__ void k_nrm(const float* __restrict__ bnw, const float* __restrict__ bnb) {
    int t = threadIdx.x;
    if (t < NS) {
        float mu = g_stat[t] * (1.f / NN);
        float var = g_stat[NS + t] * (1.f / NN) - mu * mu;
        float sc = bnw[t] * rsqrtf(var + EPSF);
        g_nrm[t] = sc; g_nrm[NS + t] = bnb[t] - mu * sc;
    } else if (t < NS + NV) {
        int i = t - NS;
        float fn = g_stat[2 * NS + i] * (1.f / (3.f * NN));
        g_nrm[2 * NS + i] = bnw[NS + i] * rsqrtf(fn + EPSF);
    }
}
__global__ void k_apply(float* __restrict__ out) {
    int i = blockIdx.x * blockDim.x + threadIdx.x, st = gridDim.x * blockDim.x;
    for (int x = i; x < NN * IND; x += st) {
        int n = x / IND, d = x - n * IND;
        out[x] = (d < NS) ? g_pre[x] * g_nrm[d] + g_nrm[NS + d]
                          : g_pre[x] * g_nrm[2 * NS + (d - NS) / 3];
    }
}

extern "C" void kernel_launch(void* const* d_in, const int* in_sizes, int n_in,
                              void* d_out, int out_size) {
    (void)in_sizes; (void)n_in; (void)out_size;
    const float* nattr = (const float*)d_in[0];
    const float* ea    = (const float*)d_in[1];
    const float* esh   = (const float*)d_in[2];
    const float* w1    = (const float*)d_in[3];
    const float* b1    = (const float*)d_in[4];
    const float* w2    = (const float*)d_in[5];
    const float* b2    = (const float*)d_in[6];
    const float* bnw   = (const float*)d_in[7];
    const float* bnb   = (const float*)d_in[8];
    const int*   ei    = (const int*)d_in[9];
    float* out = (float*)d_out;

    size_t sm1 = (size_t)(19008 + 20736) * 4;
    cudaFuncSetAttribute(k_fc1,  cudaFuncAttributeMaxDynamicSharedMemorySize, (int)sm1);
    cudaFuncSetAttribute(k_main, cudaFuncAttributeMaxDynamicSharedMemorySize, SMEMTOT);

    k_zero<<<512, 256>>>();
    k_wprep<<<(NCH * NF * 48 + 255) / 256, 256>>>(w2);
    k_fc1<<<NBLK, 256, sm1>>>(ea, w1, b1);
    k_main<<<NBLK, NTH, SMEMTOT>>>(nattr, esh, b2, ei);
    k_pre<<<512, 256>>>(nattr);
    k_stat<<<NS + NV, 256>>>();
    k_nrm<<<1, 64>>>(bnw, bnb);
    k_apply<<<512, 256>>>(out);
}

// round 14
// speedup vs baseline: 2.4450x; 1.2582x over previous
#include <cuda_runtime.h>
#include <cuda_fp16.h>
#include <stdint.h>
#include <math.h>

#define NS 48
#define NV 10
#define NE 100000
#define NN 10000
#define NF 144
#define IND 78
#define WNUM 3364
#define EPB 128
#define NBLK ((NE + EPB - 1) / EPB)
#define NCH 71
#define NTH 384
#define A_SS 0.102062072615966f
#define A_VV 0.223606797749979f
#define ISQ3 0.577350269189626f
#define EPSF 1e-5f

/* ---- SMEM byte offsets (k_main) ---- */
#define OFF_B    0          /* [2 buf][16128] = 32256 */
#define OFF_BIAS 32256      /* [71][48] f32 = 13632 */
#define OFF_CS   45888      /* [128][58] f32 = 29696 */
#define OFF_U    75584      /* [128][48] f32 = 24576 */
#define OFF_V    100160     /* [128][30] f32 = 15360 */
#define OFF_S0   115520     /* [128] f32 */
#define OFF_S1   116032     /* [128][3] f32 */
#define OFF_SS   117568     /* [128] int */
#define OFF_AP   118080     /* [128][10] f32 */
#define OFF_AQ   123200     /* [128][30] f32 */
#define SMEMTOT  138560
#define SMEM_FC1 32832      /* B bufs 32256 + b1 144*4 */

__device__ float g_h[(size_t)NE * NF];
__device__ __half g_whl[(size_t)NCH * NF * 48];  /* fc2 chunks: [144][48] fp16 */
__device__ __half g_w1f[(size_t)3 * NF * 48];    /* fc1 chunks: [144][48] fp16 */
__device__ float g_sum[NN * IND];
__device__ float g_cnt[NN];
__device__ float g_pre[NN * IND];
__device__ float g_stat[2 * NS + NV];
__device__ float g_nrm[2 * NS + NV];

__device__ __forceinline__ uint32_t smem_u32(const void* p) {
    uint32_t a;
    asm("{ .reg .u64 t; cvta.to.shared.u64 t, %1; cvt.u32.u64 %0, t; }" : "=r"(a) : "l"(p));
    return a;
}
__device__ __forceinline__ void ldsm4t(uint32_t* r, uint32_t a) {
    asm volatile("ldmatrix.sync.aligned.m8n8.x4.trans.shared.b16 {%0,%1,%2,%3}, [%4];"
                 : "=r"(r[0]), "=r"(r[1]), "=r"(r[2]), "=r"(r[3]) : "r"(a));
}
__device__ __forceinline__ void mma16816(float* d, const uint32_t* a,
                                         uint32_t b0, uint32_t b1) {
    asm volatile("mma.sync.aligned.m16n8k16.row.col.f32.f16.f16.f32 "
                 "{%0,%1,%2,%3}, {%4,%5,%6,%7}, {%8,%9}, {%0,%1,%2,%3};"
                 : "+f"(d[0]), "+f"(d[1]), "+f"(d[2]), "+f"(d[3])
                 : "r"(a[0]), "r"(a[1]), "r"(a[2]), "r"(a[3]), "r"(b0), "r"(b1));
}
__device__ __forceinline__ void cpa16(uint32_t dst, const void* src) {
    asm volatile("cp.async.cg.shared.global [%0], [%1], 16;" :: "r"(dst), "l"(src));
}
#define CPA_COMMIT() asm volatile("cp.async.commit_group;" ::: "memory")
#define CPA_WAIT0()  asm volatile("cp.async.wait_group 0;" ::: "memory")
__device__ __forceinline__ uint32_t pkh(float x0, float x1) {
    __half h0 = __float2half_rn(x0), h1 = __float2half_rn(x1);
    return (uint32_t)__half_as_ushort(h0) | ((uint32_t)__half_as_ushort(h1) << 16);
}

/* -------- w2 -> fp16 chunk blob -------- */
__global__ void k_wprep(const float* __restrict__ w2) {
    int x = blockIdx.x * blockDim.x + threadIdx.x;
    if (x < NCH * NF * 48) {
        int n = x % 48, t = x / 48, k = t % NF, ch = t / NF;
        int gc = ch * 48 + n;
        float v = (gc < WNUM) ? w2[(size_t)k * WNUM + gc] : 0.f;
        g_whl[x] = __float2half_rn(v);
    }
}
/* -------- w1 -> fp16 chunk blob (3 chunks of 48 cols) -------- */
__global__ void k_wprep1(const float* __restrict__ w1) {
    int x = blockIdx.x * blockDim.x + threadIdx.x;
    if (x < 3 * NF * 48) {
        int n = x % 48, t = x / 48, k = t % NF, ch = t / NF;
        g_w1f[x] = __float2half_rn(w1[k * NF + ch * 48 + n]);
    }
}

/* -------- fc1 via fp16 mma: h = relu(ea@w1 + b1) -> g_h -------- */
__global__ __launch_bounds__(NTH, 1) void k_fc1m(const float* __restrict__ ea,
                                                 const float* __restrict__ b1) {
    extern __shared__ char smc[];
    uint32_t smb = smem_u32(smc);
    float* sB1 = (float*)(smc + 32256);

    int tid = threadIdx.x, lane = tid & 31, warp = tid >> 5;
    int gid = lane >> 2, tig = lane & 3;
    int eg = warp / 3, cg = warp % 3;
    int e0 = blockIdx.x * EPB;

    if (tid < NF) sB1[tid] = b1[tid];

    /* A fragments from edge_attr, fp16 */
    uint32_t AH[2][9][4];
#pragma unroll
    for (int mt = 0; mt < 2; mt++) {
        int r0 = eg * 32 + mt * 16 + gid;
#pragma unroll
        for (int kt = 0; kt < 9; kt++) {
#pragma unroll
            for (int q = 0; q < 4; q++) {
                int row = r0 + (q & 1) * 8;
                int k = kt * 16 + tig * 2 + (q >> 1) * 8;
                float f0 = 0.f, f1 = 0.f;
                if (e0 + row < NE) {
                    const float* p = &ea[(size_t)(e0 + row) * NF + k];
                    f0 = p[0]; f1 = p[1];
                }
                AH[mt][kt][q] = pkh(f0, f1);
            }
        }
    }

    uint32_t a4 = smb + cg * 32 + (lane & 15) * 112 + (lane >> 4) * 16;

    /* prologue fill chunk 0 */
    {
        const char* src = (const char*)g_w1f;
        for (int x = tid; x < 864; x += NTH) {
            int k = x / 6, part = x - k * 6;
            cpa16(smb + k * 112 + part * 16, src + k * 96 + part * 16);
        }
        CPA_COMMIT();
    }

    for (int cc = 0; cc < 3; cc++) {
        int buf = cc & 1;
        CPA_WAIT0();
        __syncthreads();
        if (cc + 1 < 3) {
            const char* src = (const char*)g_w1f + (size_t)(cc + 1) * 13824;
            uint32_t dstb = smb + (buf ^ 1) * 16128;
            for (int x = tid; x < 864; x += NTH) {
                int k = x / 6, part = x - k * 6;
                cpa16(dstb + k * 112 + part * 16, src + k * 96 + part * 16);
            }
            CPA_COMMIT();
        }

        float d[2][2][4];
#pragma unroll
        for (int mt = 0; mt < 2; mt++)
#pragma unroll
            for (int nt = 0; nt < 2; nt++)
#pragma unroll
                for (int q = 0; q < 4; q++) d[mt][nt][q] = 0.f;

        uint32_t bofs = buf * 16128;
        uint32_t bh[4];
        ldsm4t(bh, a4 + bofs);
#pragma unroll
        for (int kt = 0; kt < 9; kt++) {
            uint32_t nh[4];
            if (kt < 8) ldsm4t(nh, a4 + bofs + (kt + 1) * 1792);
#pragma unroll
            for (int mt = 0; mt < 2; mt++) {
                mma16816(d[mt][0], AH[mt][kt], bh[0], bh[1]);
                mma16816(d[mt][1], AH[mt][kt], bh[2], bh[3]);
            }
            if (kt < 8) {
#pragma unroll
                for (int q = 0; q < 4; q++) bh[q] = nh[q];
            }
        }

        /* epilogue: +bias, relu, store h */
#pragma unroll
        for (int mt = 0; mt < 2; mt++) {
            int er0 = eg * 32 + mt * 16 + gid;
#pragma unroll
            for (int nt = 0; nt < 2; nt++) {
                int gcol = cc * 48 + cg * 16 + nt * 8 + tig * 2;
                float b0v = sB1[gcol], b1v = sB1[gcol + 1];
                if (e0 + er0 < NE) {
                    float2 h0 = make_float2(fmaxf(d[mt][nt][0] + b0v, 0.f),
                                            fmaxf(d[mt][nt][1] + b1v, 0.f));
                    *(float2*)&g_h[(size_t)(e0 + er0) * NF + gcol] = h0;
                }
                if (e0 + er0 + 8 < NE) {
                    float2 h1 = make_float2(fmaxf(d[mt][nt][2] + b0v, 0.f),
                                            fmaxf(d[mt][nt][3] + b1v, 0.f));
                    *(float2*)&g_h[(size_t)(e0 + er0 + 8) * NF + gcol] = h1;
                }
            }
        }
    }
}

/* -------- fused fc2: fp16 mma single-product, 12 warps, cp.async B -------- */
__global__ __launch_bounds__(NTH, 1) void k_main(const float* __restrict__ na,
                                                 const float* __restrict__ esh,
                                                 const float* __restrict__ b2,
                                                 const int* __restrict__ ei) {
    extern __shared__ char smc[];
    uint32_t smb = smem_u32(smc);
    float* sBias = (float*)(smc + OFF_BIAS);
    float* sCS = (float*)(smc + OFF_CS);
    float* sU  = (float*)(smc + OFF_U);
    float* sV  = (float*)(smc + OFF_V);
    float* s0  = (float*)(smc + OFF_S0);
    float* s1  = (float*)(smc + OFF_S1);
    int*   sS  = (int*)(smc + OFF_SS);
    float* aP  = (float*)(smc + OFF_AP);
    float* aQ  = (float*)(smc + OFF_AQ);

    int tid = threadIdx.x, lane = tid & 31, warp = tid >> 5;
    int gid = lane >> 2, tig = lane & 3;
    int eg = warp / 3, cg = warp % 3;
    int e0 = blockIdx.x * EPB;

    for (int x = tid; x < EPB * IND; x += NTH) {
        int e = x / IND, d = x - e * IND;
        float v = 0.f;
        if (e0 + e < NE) { int dst = ei[NE + e0 + e]; v = na[dst * IND + d]; }
        if (d < NS) sU[e * NS + d] = A_SS * v;
        else        sV[e * 30 + d - NS] = A_VV * v;
    }
    if (tid < EPB) {
        int egl = e0 + tid;
        if (egl < NE) {
            sS[tid] = ei[egl]; s0[tid] = esh[egl * 4];
            s1[tid * 3] = esh[egl * 4 + 1]; s1[tid * 3 + 1] = esh[egl * 4 + 2];
            s1[tid * 3 + 2] = esh[egl * 4 + 3];
        } else {
            sS[tid] = 0; s0[tid] = 0.f;
            s1[tid * 3] = s1[tid * 3 + 1] = s1[tid * 3 + 2] = 0.f;
        }
    }
    for (int x = tid; x < EPB * 40; x += NTH) aP[x] = 0.f;
    for (int x = tid; x < NCH * 48; x += NTH)
        sBias[x] = (x < WNUM) ? b2[x] : 0.f;
    __syncthreads();
    for (int x = tid; x < EPB * 58; x += NTH) {
        int e = x / 58, i = x - e * 58;
        if (i < 48) sCS[x] = s0[e] * sU[e * 48 + i];
        else {
            int ii = i - 48;
            sCS[x] = ISQ3 * (sV[e * 30 + ii * 3] * s1[e * 3] +
                             sV[e * 30 + ii * 3 + 1] * s1[e * 3 + 1] +
                             sV[e * 30 + ii * 3 + 2] * s1[e * 3 + 2]);
        }
    }

    uint32_t AH[2][9][4];
#pragma unroll
    for (int mt = 0; mt < 2; mt++) {
        int r0 = eg * 32 + mt * 16 + gid;
#pragma unroll
        for (int kt = 0; kt < 9; kt++) {
#pragma unroll
            for (int q = 0; q < 4; q++) {
                int row = r0 + (q & 1) * 8;
                int k = kt * 16 + tig * 2 + (q >> 1) * 8;
                float f0 = 0.f, f1 = 0.f;
                if (e0 + row < NE) {
                    const float* p = &g_h[(size_t)(e0 + row) * NF + k];
                    f0 = p[0]; f1 = p[1];
                }
                AH[mt][kt][q] = pkh(f0, f1);
            }
        }
    }

    uint32_t a4 = smb + OFF_B + cg * 32 + (lane & 15) * 112 + (lane >> 4) * 16;

    float acc[2][2][4];
#pragma unroll
    for (int mt = 0; mt < 2; mt++)
#pragma unroll
        for (int nt = 0; nt < 2; nt++)
#pragma unroll
            for (int q = 0; q < 4; q++) acc[mt][nt][q] = 0.f;

    {
        const char* src = (const char*)g_whl;
        for (int x = tid; x < 864; x += NTH) {
            int k = x / 6, part = x - k * 6;
            cpa16(smb + OFF_B + k * 112 + part * 16, src + k * 96 + part * 16);
        }
        CPA_COMMIT();
    }

    for (int cc = 0; cc < NCH; cc++) {
        int buf = cc & 1;
        CPA_WAIT0();
        __syncthreads();
        if (cc + 1 < NCH) {
            const char* src = (const char*)g_whl + (size_t)(cc + 1) * 13824;
            uint32_t dstb = smb + OFF_B + (buf ^ 1) * 16128;
            for (int x = tid; x < 864; x += NTH) {
                int k = x / 6, part = x - k * 6;
                cpa16(dstb + k * 112 + part * 16, src + k * 96 + part * 16);
            }
            CPA_COMMIT();
        }

        float d[2][2][4];
#pragma unroll
        for (int mt = 0; mt < 2; mt++)
#pragma unroll
            for (int nt = 0; nt < 2; nt++)
#pragma unroll
                for (int q = 0; q < 4; q++) d[mt][nt][q] = 0.f;

        uint32_t bofs = buf * 16128;
        uint32_t bh[4];
        ldsm4t(bh, a4 + bofs);
#pragma unroll
        for (int kt = 0; kt < 9; kt++) {
            uint32_t nh[4];
            if (kt < 8) ldsm4t(nh, a4 + bofs + (kt + 1) * 1792);
#pragma unroll
            for (int mt = 0; mt < 2; mt++) {
                mma16816(d[mt][0], AH[mt][kt], bh[0], bh[1]);
                mma16816(d[mt][1], AH[mt][kt], bh[2], bh[3]);
            }
            if (kt < 8) {
#pragma unroll
                for (int q = 0; q < 4; q++) bh[q] = nh[q];
            }
        }

        const float* bp = sBias + cc * 48;
        if (cc < 58) {
#pragma unroll
            for (int mt = 0; mt < 2; mt++) {
                int er0 = eg * 32 + mt * 16 + gid;
                float cf0 = sCS[er0 * 58 + cc], cf1 = sCS[(er0 + 8) * 58 + cc];
#pragma unroll
                for (int nt = 0; nt < 2; nt++) {
                    int col = cg * 16 + nt * 8 + tig * 2;
                    float b0v = bp[col], b1v = bp[col + 1];
                    acc[mt][nt][0] = fmaf(cf0, d[mt][nt][0] + b0v, acc[mt][nt][0]);
                    acc[mt][nt][1] = fmaf(cf0, d[mt][nt][1] + b1v, acc[mt][nt][1]);
                    acc[mt][nt][2] = fmaf(cf1, d[mt][nt][2] + b0v, acc[mt][nt][2]);
                    acc[mt][nt][3] = fmaf(cf1, d[mt][nt][3] + b1v, acc[mt][nt][3]);
                }
            }
        } else if (cc < 68) {
#pragma unroll
            for (int nt = 0; nt < 2; nt++) {
#pragma unroll
                for (int j = 0; j < 2; j++) {
                    int col = cg * 16 + nt * 8 + tig * 2 + j;
                    int tt = (cc - 58) * 48 + col;
                    int i = tt / 10, o = tt - i * 10;
                    float bb = bp[col];
#pragma unroll
                    for (int mt = 0; mt < 2; mt++) {
                        int er0 = eg * 32 + mt * 16 + gid;
                        atomicAdd(&aP[er0 * 10 + o],
                                  sU[er0 * 48 + i] * (d[mt][nt][j] + bb));
                        atomicAdd(&aP[(er0 + 8) * 10 + o],
                                  sU[(er0 + 8) * 48 + i] * (d[mt][nt][2 + j] + bb));
                    }
                }
            }
        } else {
#pragma unroll
            for (int nt = 0; nt < 2; nt++) {
#pragma unroll
                for (int j = 0; j < 2; j++) {
                    int col = cg * 16 + nt * 8 + tig * 2 + j;
                    int tt = (cc - 68) * 48 + col;
                    if (tt < 100) {
                        int i = tt / 10, o = tt - i * 10;
                        float bb = bp[col];
#pragma unroll
                        for (int mt = 0; mt < 2; mt++) {
                            int er0 = eg * 32 + mt * 16 + gid;
                            float w0 = d[mt][nt][j] + bb;
                            float w1v = d[mt][nt][2 + j] + bb;
                            const float* vp0 = &sV[er0 * 30 + i * 3];
                            const float* vp1 = &sV[(er0 + 8) * 30 + i * 3];
                            atomicAdd(&aQ[er0 * 30 + o * 3],     vp0[0] * w0);
                            atomicAdd(&aQ[er0 * 30 + o * 3 + 1], vp0[1] * w0);
                            atomicAdd(&aQ[er0 * 30 + o * 3 + 2], vp0[2] * w0);
                            atomicAdd(&aQ[(er0 + 8) * 30 + o * 3],     vp1[0] * w1v);
                            atomicAdd(&aQ[(er0 + 8) * 30 + o * 3 + 1], vp1[1] * w1v);
                            atomicAdd(&aQ[(er0 + 8) * 30 + o * 3 + 2], vp1[2] * w1v);
                        }
                    }
                }
            }
        }
    }
    __syncthreads();

#pragma unroll
    for (int mt = 0; mt < 2; mt++) {
        int er0 = eg * 32 + mt * 16 + gid;
        int eg0 = e0 + er0, eg1 = eg0 + 8;
        int base0 = sS[er0] * IND, base1 = sS[er0 + 8] * IND;
#pragma unroll
        for (int nt = 0; nt < 2; nt++) {
#pragma unroll
            for (int j = 0; j < 2; j++) {
                int col = cg * 16 + nt * 8 + tig * 2 + j;
                if (eg0 < NE) atomicAdd(&g_sum[base0 + col], acc[mt][nt][j]);
                if (eg1 < NE) atomicAdd(&g_sum[base1 + col], acc[mt][nt][2 + j]);
            }
        }
    }
    for (int x = tid; x < EPB * 30; x += NTH) {
        int e = x / 30, t = x - e * 30, o = t / 3, ccp = t - o * 3;
        if (e0 + e < NE) {
            float v = s1[e * 3 + ccp] * aP[e * 10 + o] + s0[e] * aQ[e * 30 + t];
            atomicAdd(&g_sum[sS[e] * IND + NS + t], v);
        }
    }
    if (tid < EPB && e0 + tid < NE) atomicAdd(&g_cnt[sS[tid]], 1.f);
}

/* ---------------- epilogue ---------------- */
__global__ void k_zero() {
    int i = blockIdx.x * blockDim.x + threadIdx.x, st = gridDim.x * blockDim.x;
    for (int x = i; x < NN * IND; x += st) g_sum[x] = 0.f;
    for (int x = i; x < NN; x += st) g_cnt[x] = 0.f;
    if (i < 2 * NS + NV) g_stat[i] = 0.f;
}
__global__ void k_pre(const float* __restrict__ na) {
    int i = blockIdx.x * blockDim.x + threadIdx.x, st = gridDim.x * blockDim.x;
    for (int x = i; x < NN * IND; x += st) {
        int n = x / IND;
        g_pre[x] = g_sum[x] / fmaxf(g_cnt[n], 1.f) + na[x];
    }
}
__global__ __launch_bounds__(256) void k_stat() {
    __shared__ float r1[256], r2[256];
    int b = blockIdx.x, tid = threadIdx.x;
    float s = 0.f, q = 0.f;
    if (b < NS) {
        for (int n = tid; n < NN; n += 256) { float v = g_pre[n * IND + b]; s += v; q += v * v; }
    } else {
        int i = b - NS;
        for (int n = tid; n < NN; n += 256) {
            const float* p = &g_pre[n * IND + NS + i * 3];
            s += p[0] * p[0] + p[1] * p[1] + p[2] * p[2];
        }
    }
    r1[tid] = s; r2[tid] = q; __syncthreads();
    for (int o = 128; o > 0; o >>= 1) {
        if (tid < o) { r1[tid] += r1[tid + o]; r2[tid] += r2[tid + o]; }
        __syncthreads();
    }
    if (tid == 0) {
        if (b < NS) { g_stat[b] = r1[0]; g_stat[NS + b] = r2[0]; }
        else g_stat[NS + b] = r1[0];
    }
}
__global__ void k_nrm(const float* __restrict__ bnw, const float* __restrict__ bnb) {
    int t = threadIdx.x;
    if (t < NS) {
        float mu = g_stat[t] * (1.f / NN);
        float var = g_stat[NS + t] * (1.f / NN) - mu * mu;
        float sc = bnw[t] * rsqrtf(var + EPSF);
        g_nrm[t] = sc; g_nrm[NS + t] = bnb[t] - mu * sc;
    } else if (t < NS + NV) {
        int i = t - NS;
        float fn = g_stat[2 * NS + i] * (1.f / (3.f * NN));
        g_nrm[2 * NS + i] = bnw[NS + i] * rsqrtf(fn + EPSF);
    }
}
__global__ void k_apply(float* __restrict__ out) {
    int i = blockIdx.x * blockDim.x + threadIdx.x, st = gridDim.x * blockDim.x;
    for (int x = i; x < NN * IND; x += st) {
        int n = x / IND, d = x - n * IND;
        out[x] = (d < NS) ? g_pre[x] * g_nrm[d] + g_nrm[NS + d]
                          : g_pre[x] * g_nrm[2 * NS + (d - NS) / 3];
    }
}

extern "C" void kernel_launch(void* const* d_in, const int* in_sizes, int n_in,
                              void* d_out, int out_size) {
    (void)in_sizes; (void)n_in; (void)out_size;
    const float* nattr = (const float*)d_in[0];
    const float* ea    = (const float*)d_in[1];
    const float* esh   = (const float*)d_in[2];
    const float* w1    = (const float*)d_in[3];
    const float* b1    = (const float*)d_in[4];
    const float* w2    = (const float*)d_in[5];
    const float* b2    = (const float*)d_in[6];
    const float* bnw   = (const float*)d_in[7];
    const float* bnb   = (const float*)d_in[8];
    const int*   ei    = (const int*)d_in[9];
    float* out = (float*)d_out;

    cudaFuncSetAttribute(k_fc1m, cudaFuncAttributeMaxDynamicSharedMemorySize, SMEM_FC1);
    cudaFuncSetAttribute(k_main, cudaFuncAttributeMaxDynamicSharedMemorySize, SMEMTOT);

    k_zero<<<512, 256>>>();
    k_wprep<<<(NCH * NF * 48 + 255) / 256, 256>>>(w2);
    k_wprep1<<<(3 * NF * 48 + 255) / 256, 256>>>(w1);
    k_fc1m<<<NBLK, NTH, SMEM_FC1>>>(ea, b1);
    k_main<<<NBLK, NTH, SMEMTOT>>>(nattr, esh, b2, ei);
    k_pre<<<512, 256>>>(nattr);
    k_stat<<<NS + NV, 256>>>();
    k_nrm<<<1, 64>>>(bnw, bnb);
    k_apply<<<512, 256>>>(out);
}